// round 5
// baseline (speedup 1.0000x reference)
#include <cuda_runtime.h>
#include <cuda_fp16.h>
#include <math_constants.h>

#define N_NODES 50000
#define N_EDGES 1600000
#define IN_DIM  128
#define HEADS   4
#define HID     16
#define HD      64              // HEADS*HID
#define NEG_SLOPE 0.2f

// ---------------- scratch (device globals) ----------------------------------
__device__ __half g_feat_h[N_NODES * HD];   // projected features, fp16
__device__ float  g_acc  [N_NODES * HD];    // unnormalized output accumulator
__device__ float  g_el   [N_NODES * HEADS];
__device__ float  g_er   [N_NODES * HEADS];
__device__ float  g_denom[N_NODES * HEADS];
__device__ int    g_src  [N_EDGES];
__device__ int    g_dst  [N_EDGES];

__device__ __forceinline__ float lrelu(float x) {
    return x > 0.0f ? x : NEG_SLOPE * x;
}

// ---------------- K-convert: probe dtype, convert indices, zero scratch ----
__global__ void k_convert(const void* s_raw, const void* d_raw) {
    __shared__ int is64s;
    if (threadIdx.x == 0) is64s = 1;
    __syncthreads();
    {
        // If the data is really int32, these 64-bit words carry a random
        // index in the upper half — guaranteed >= N_NODES among 256 samples.
        unsigned long long v = ((const unsigned long long*)s_raw)[threadIdx.x];
        if (v >= (unsigned long long)N_NODES) atomicExch(&is64s, 0);
    }
    __syncthreads();
    const bool is64 = (is64s != 0);

    int i = blockIdx.x * blockDim.x + threadIdx.x;

    // zero accumulators (prefix threads; plenty of threads available)
    const float4 z = make_float4(0.f, 0.f, 0.f, 0.f);
    if (i < (N_NODES * HD) / 4)    ((float4*)g_acc)[i]   = z;
    if (i < (N_NODES * HEADS) / 4) ((float4*)g_denom)[i] = z;

    if (i >= N_EDGES) return;
    if (is64) {
        g_src[i] = (int)((const long long*)s_raw)[i];
        g_dst[i] = (int)((const long long*)d_raw)[i];
    } else {
        g_src[i] = ((const int*)s_raw)[i];
        g_dst[i] = ((const int*)d_raw)[i];
    }
}

// ---------------- K1: GEMM feat = X @ W, fused el/er + fp16 store -----------
#define BM 64
#define KC 64
#define XPAD 68

__global__ void __launch_bounds__(256) k_gemm(const float* __restrict__ X,
                                              const float* __restrict__ W,
                                              const float* __restrict__ attn_l,
                                              const float* __restrict__ attn_r) {
    __shared__ float sW [KC * HD];     // 16 KB
    __shared__ float sXt[KC * XPAD];   // 17 KB
    const int tid  = threadIdx.x;
    const int row0 = blockIdx.x * BM;
    const int r0   = (tid >> 4) << 2;  // 0,4,..,60
    const int c0   = (tid & 15) << 2;  // 0,4,..,60

    float acc[4][4] = {};

    for (int k0 = 0; k0 < IN_DIM; k0 += KC) {
        #pragma unroll
        for (int i = tid; i < KC * HD; i += 256) {
            int k = i >> 6, c = i & 63;
            sW[i] = W[(k0 + k) * HD + c];
        }
        #pragma unroll
        for (int i = tid; i < BM * KC; i += 256) {
            int r = i >> 6, k = i & 63;
            int gr = row0 + r;
            float v = (gr < N_NODES) ? X[gr * IN_DIM + k0 + k] : 0.0f;
            sXt[k * XPAD + r] = v;
        }
        __syncthreads();

        #pragma unroll 8
        for (int k = 0; k < KC; k++) {
            float4 xv = *(const float4*)&sXt[k * XPAD + r0];
            float4 wv = *(const float4*)&sW [k * HD   + c0];
            acc[0][0] = fmaf(xv.x, wv.x, acc[0][0]);
            acc[0][1] = fmaf(xv.x, wv.y, acc[0][1]);
            acc[0][2] = fmaf(xv.x, wv.z, acc[0][2]);
            acc[0][3] = fmaf(xv.x, wv.w, acc[0][3]);
            acc[1][0] = fmaf(xv.y, wv.x, acc[1][0]);
            acc[1][1] = fmaf(xv.y, wv.y, acc[1][1]);
            acc[1][2] = fmaf(xv.y, wv.z, acc[1][2]);
            acc[1][3] = fmaf(xv.y, wv.w, acc[1][3]);
            acc[2][0] = fmaf(xv.z, wv.x, acc[2][0]);
            acc[2][1] = fmaf(xv.z, wv.y, acc[2][1]);
            acc[2][2] = fmaf(xv.z, wv.z, acc[2][2]);
            acc[2][3] = fmaf(xv.z, wv.w, acc[2][3]);
            acc[3][0] = fmaf(xv.w, wv.x, acc[3][0]);
            acc[3][1] = fmaf(xv.w, wv.y, acc[3][1]);
            acc[3][2] = fmaf(xv.w, wv.z, acc[3][2]);
            acc[3][3] = fmaf(xv.w, wv.w, acc[3][3]);
        }
        __syncthreads();
    }

    const float4 al4 = *(const float4*)&attn_l[c0];
    const float4 ar4 = *(const float4*)&attn_r[c0];
    const int head = (tid >> 2) & 3;

    #pragma unroll
    for (int i = 0; i < 4; i++) {
        int r = row0 + r0 + i;
        if (r < N_NODES) {
            __half2 h0 = __float22half2_rn(make_float2(acc[i][0], acc[i][1]));
            __half2 h1 = __float22half2_rn(make_float2(acc[i][2], acc[i][3]));
            uint2 pk = make_uint2(*(unsigned*)&h0, *(unsigned*)&h1);
            *(uint2*)&g_feat_h[r * HD + c0] = pk;
        }

        float el = acc[i][0] * al4.x + acc[i][1] * al4.y
                 + acc[i][2] * al4.z + acc[i][3] * al4.w;
        float er = acc[i][0] * ar4.x + acc[i][1] * ar4.y
                 + acc[i][2] * ar4.z + acc[i][3] * ar4.w;
        el += __shfl_xor_sync(0xffffffffu, el, 1);
        el += __shfl_xor_sync(0xffffffffu, el, 2);
        er += __shfl_xor_sync(0xffffffffu, er, 1);
        er += __shfl_xor_sync(0xffffffffu, er, 2);
        if ((tid & 3) == 0 && r < N_NODES) {
            g_el[r * HEADS + head] = el;
            g_er[r * HEADS + head] = er;
        }
    }
}

// ---------------- K2: fused edge pass, 8 threads / edge ---------------------
// ee = exp(lrelu(el[s]+er[d])) (no max-shift: |logit| small, exp safe);
// scatter UNNORMALIZED ee*feat_h[src] into g_acc, ee into g_denom.
__global__ void k_edge() {
    int idx = blockIdx.x * blockDim.x + threadIdx.x;
    int e = idx >> 3;
    if (e >= N_EDGES) return;
    int t = idx & 7;            // owns halfs [t*8, t*8+8); head h = t>>1
    int h = t >> 1;
    int s = g_src[e], d = g_dst[e];

    float ee = __expf(lrelu(g_el[s * HEADS + h] + g_er[d * HEADS + h]));

    uint4 pk = *(const uint4*)&g_feat_h[s * HD + t * 8];
    float2 f0 = __half22float2(*(__half2*)&pk.x);
    float2 f1 = __half22float2(*(__half2*)&pk.y);
    float2 f2 = __half22float2(*(__half2*)&pk.z);
    float2 f3 = __half22float2(*(__half2*)&pk.w);

    float* dstp = &g_acc[d * HD + t * 8];
    atomicAdd((float4*)dstp,
              make_float4(f0.x * ee, f0.y * ee, f1.x * ee, f1.y * ee));
    atomicAdd((float4*)(dstp + 4),
              make_float4(f2.x * ee, f2.y * ee, f3.x * ee, f3.y * ee));
    if ((t & 1) == 0)
        atomicAdd(&g_denom[d * HEADS + h], ee);
}

// ---------------- K3: normalize + head mean + bias (coalesced) --------------
__global__ void k_final(const float* __restrict__ bias, float* __restrict__ out) {
    int i = blockIdx.x * blockDim.x + threadIdx.x;
    if (i >= N_NODES * 16) return;
    int n = i >> 4, j = i & 15;       // j: float4 chunk within node row
    int h = j >> 2;                   // head of this chunk

    float4 v = *(const float4*)&g_acc[n * HD + j * 4];
    float den = g_denom[n * HEADS + h];
    float inv = (den > 0.0f) ? __fdividef(0.25f, den) : 0.0f;
    v.x *= inv; v.y *= inv; v.z *= inv; v.w *= inv;

    // sum across heads: partners at lanes j^4 and j^8 (16-lane groups per node)
    v.x += __shfl_xor_sync(0xffffffffu, v.x, 4);
    v.y += __shfl_xor_sync(0xffffffffu, v.y, 4);
    v.z += __shfl_xor_sync(0xffffffffu, v.z, 4);
    v.w += __shfl_xor_sync(0xffffffffu, v.w, 4);
    v.x += __shfl_xor_sync(0xffffffffu, v.x, 8);
    v.y += __shfl_xor_sync(0xffffffffu, v.y, 8);
    v.z += __shfl_xor_sync(0xffffffffu, v.z, 8);
    v.w += __shfl_xor_sync(0xffffffffu, v.w, 8);

    if (j < 4) {
        int c = j * 4;
        float4 b0 = *(const float4*)&bias[c];
        float4 b1 = *(const float4*)&bias[HID + c];
        float4 b2 = *(const float4*)&bias[2 * HID + c];
        float4 b3 = *(const float4*)&bias[3 * HID + c];
        float4 o;
        o.x = v.x + 0.25f * (b0.x + b1.x + b2.x + b3.x);
        o.y = v.y + 0.25f * (b0.y + b1.y + b2.y + b3.y);
        o.z = v.z + 0.25f * (b0.z + b1.z + b2.z + b3.z);
        o.w = v.w + 0.25f * (b0.w + b1.w + b2.w + b3.w);
        *(float4*)&out[n * HID + c] = o;
    }
}

// ---------------- launch ------------------------------------------------------
extern "C" void kernel_launch(void* const* d_in, const int* in_sizes, int n_in,
                              void* d_out, int out_size) {
    const float* features = (const float*)d_in[0];
    const float* W        = (const float*)d_in[1];
    const float* attn_l   = (const float*)d_in[2];
    const float* attn_r   = (const float*)d_in[3];
    const float* bias     = (const float*)d_in[4];
    const void*  src_raw  = d_in[5];
    const void*  dst_raw  = d_in[6];
    float* out = (float*)d_out;

    const int T = 256;

    k_convert<<<(N_EDGES + T - 1) / T, T>>>(src_raw, dst_raw);
    k_gemm<<<(N_NODES + BM - 1) / BM, T>>>(features, W, attn_l, attn_r);
    k_edge<<<((long long)N_EDGES * 8 + T - 1) / T, T>>>();
    k_final<<<(N_NODES * 16 + T - 1) / T, T>>>(bias, out);
}

// round 6
// speedup vs baseline: 1.1606x; 1.1606x over previous
#include <cuda_runtime.h>
#include <cuda_fp16.h>
#include <math_constants.h>

#define N_NODES 50000
#define N_EDGES 1600000
#define IN_DIM  128
#define HEADS   4
#define HID     16
#define HD      64              // HEADS*HID
#define NEG_SLOPE 0.2f

// ---------------- scratch (device globals) ----------------------------------
__device__ __half g_feat_h[N_NODES * HD];   // projected features, fp16
__device__ float  g_acc  [N_NODES * HD];    // unnormalized output accumulator
__device__ float  g_el   [N_NODES * HEADS];
__device__ float  g_er   [N_NODES * HEADS];
__device__ float  g_denom[N_NODES * HEADS];
__device__ int    g_src  [N_EDGES];
__device__ int    g_dst  [N_EDGES];

__device__ __forceinline__ float lrelu(float x) {
    return x > 0.0f ? x : NEG_SLOPE * x;
}

// ---------------- K-convert: probe dtype, convert indices, zero scratch ----
__global__ void k_convert(const void* s_raw, const void* d_raw) {
    __shared__ int is64s;
    if (threadIdx.x == 0) is64s = 1;
    __syncthreads();
    {
        // If the data is really int32, these 64-bit words carry a random
        // index in the upper half — guaranteed >= N_NODES among 256 samples.
        unsigned long long v = ((const unsigned long long*)s_raw)[threadIdx.x];
        if (v >= (unsigned long long)N_NODES) atomicExch(&is64s, 0);
    }
    __syncthreads();
    const bool is64 = (is64s != 0);

    int i = blockIdx.x * blockDim.x + threadIdx.x;

    // zero accumulators (prefix threads)
    const float4 z = make_float4(0.f, 0.f, 0.f, 0.f);
    if (i < (N_NODES * HD) / 4)    ((float4*)g_acc)[i]   = z;
    if (i < (N_NODES * HEADS) / 4) ((float4*)g_denom)[i] = z;

    if (i >= N_EDGES) return;
    if (is64) {
        g_src[i] = (int)((const long long*)s_raw)[i];
        g_dst[i] = (int)((const long long*)d_raw)[i];
    } else {
        g_src[i] = ((const int*)s_raw)[i];
        g_dst[i] = ((const int*)d_raw)[i];
    }
}

// ---------------- K1: GEMM feat = X @ W, fused el/er + fp16 store -----------
#define BM 64
#define KC 64
#define XPAD 68

__global__ void __launch_bounds__(256) k_gemm(const float* __restrict__ X,
                                              const float* __restrict__ W,
                                              const float* __restrict__ attn_l,
                                              const float* __restrict__ attn_r) {
    __shared__ float sW [KC * HD];     // 16 KB
    __shared__ float sXt[KC * XPAD];   // 17 KB
    const int tid  = threadIdx.x;
    const int row0 = blockIdx.x * BM;
    const int r0   = (tid >> 4) << 2;  // 0,4,..,60
    const int c0   = (tid & 15) << 2;  // 0,4,..,60

    float acc[4][4] = {};

    for (int k0 = 0; k0 < IN_DIM; k0 += KC) {
        #pragma unroll
        for (int i = tid; i < KC * HD; i += 256) {
            int k = i >> 6, c = i & 63;
            sW[i] = W[(k0 + k) * HD + c];
        }
        #pragma unroll
        for (int i = tid; i < BM * KC; i += 256) {
            int r = i >> 6, k = i & 63;
            int gr = row0 + r;
            float v = (gr < N_NODES) ? X[gr * IN_DIM + k0 + k] : 0.0f;
            sXt[k * XPAD + r] = v;
        }
        __syncthreads();

        #pragma unroll 8
        for (int k = 0; k < KC; k++) {
            float4 xv = *(const float4*)&sXt[k * XPAD + r0];
            float4 wv = *(const float4*)&sW [k * HD   + c0];
            acc[0][0] = fmaf(xv.x, wv.x, acc[0][0]);
            acc[0][1] = fmaf(xv.x, wv.y, acc[0][1]);
            acc[0][2] = fmaf(xv.x, wv.z, acc[0][2]);
            acc[0][3] = fmaf(xv.x, wv.w, acc[0][3]);
            acc[1][0] = fmaf(xv.y, wv.x, acc[1][0]);
            acc[1][1] = fmaf(xv.y, wv.y, acc[1][1]);
            acc[1][2] = fmaf(xv.y, wv.z, acc[1][2]);
            acc[1][3] = fmaf(xv.y, wv.w, acc[1][3]);
            acc[2][0] = fmaf(xv.z, wv.x, acc[2][0]);
            acc[2][1] = fmaf(xv.z, wv.y, acc[2][1]);
            acc[2][2] = fmaf(xv.z, wv.z, acc[2][2]);
            acc[2][3] = fmaf(xv.z, wv.w, acc[2][3]);
            acc[3][0] = fmaf(xv.w, wv.x, acc[3][0]);
            acc[3][1] = fmaf(xv.w, wv.y, acc[3][1]);
            acc[3][2] = fmaf(xv.w, wv.z, acc[3][2]);
            acc[3][3] = fmaf(xv.w, wv.w, acc[3][3]);
        }
        __syncthreads();
    }

    const float4 al4 = *(const float4*)&attn_l[c0];
    const float4 ar4 = *(const float4*)&attn_r[c0];
    const int head = (tid >> 2) & 3;

    #pragma unroll
    for (int i = 0; i < 4; i++) {
        int r = row0 + r0 + i;
        if (r < N_NODES) {
            __half2 h0 = __float22half2_rn(make_float2(acc[i][0], acc[i][1]));
            __half2 h1 = __float22half2_rn(make_float2(acc[i][2], acc[i][3]));
            uint2 pk = make_uint2(*(unsigned*)&h0, *(unsigned*)&h1);
            *(uint2*)&g_feat_h[r * HD + c0] = pk;
        }

        float el = acc[i][0] * al4.x + acc[i][1] * al4.y
                 + acc[i][2] * al4.z + acc[i][3] * al4.w;
        float er = acc[i][0] * ar4.x + acc[i][1] * ar4.y
                 + acc[i][2] * ar4.z + acc[i][3] * ar4.w;
        el += __shfl_xor_sync(0xffffffffu, el, 1);
        el += __shfl_xor_sync(0xffffffffu, el, 2);
        er += __shfl_xor_sync(0xffffffffu, er, 1);
        er += __shfl_xor_sync(0xffffffffu, er, 2);
        if ((tid & 3) == 0 && r < N_NODES) {
            g_el[r * HEADS + head] = el;
            g_er[r * HEADS + head] = er;
        }
    }
}

// ---------------- K2: fused edge pass, 16 threads / edge --------------------
// fp16 gather (halves gather traffic) with the R4 atomic shape: ONE float4
// RED per thread at t*16B so every 32B L2 sector is covered by exactly one
// RED instruction wavefront (the R5 two-RED layout split sectors and doubled
// L2 atomic ops).
__global__ void k_edge() {
    int idx = blockIdx.x * blockDim.x + threadIdx.x;
    int e = idx >> 4;
    if (e >= N_EDGES) return;
    int t = idx & 15;           // owns floats [t*4, t*4+4); head h = t>>2
    int h = t >> 2;
    int s = g_src[e], d = g_dst[e];

    float ee = __expf(lrelu(g_el[s * HEADS + h] + g_er[d * HEADS + h]));

    uint2 pk = *(const uint2*)&g_feat_h[s * HD + t * 4];
    float2 f0 = __half22float2(*(__half2*)&pk.x);
    float2 f1 = __half22float2(*(__half2*)&pk.y);

    atomicAdd((float4*)&g_acc[d * HD + t * 4],
              make_float4(f0.x * ee, f0.y * ee, f1.x * ee, f1.y * ee));
    if ((t & 3) == 0)
        atomicAdd(&g_denom[d * HEADS + h], ee);
}

// ---------------- K3: normalize + head mean + bias (coalesced) --------------
__global__ void k_final(const float* __restrict__ bias, float* __restrict__ out) {
    int i = blockIdx.x * blockDim.x + threadIdx.x;
    if (i >= N_NODES * 16) return;
    int n = i >> 4, j = i & 15;       // j: float4 chunk within node row
    int h = j >> 2;                   // head of this chunk

    float4 v = *(const float4*)&g_acc[n * HD + j * 4];
    float den = g_denom[n * HEADS + h];
    float inv = (den > 0.0f) ? __fdividef(0.25f, den) : 0.0f;
    v.x *= inv; v.y *= inv; v.z *= inv; v.w *= inv;

    // sum across heads: partners at lanes j^4 and j^8
    v.x += __shfl_xor_sync(0xffffffffu, v.x, 4);
    v.y += __shfl_xor_sync(0xffffffffu, v.y, 4);
    v.z += __shfl_xor_sync(0xffffffffu, v.z, 4);
    v.w += __shfl_xor_sync(0xffffffffu, v.w, 4);
    v.x += __shfl_xor_sync(0xffffffffu, v.x, 8);
    v.y += __shfl_xor_sync(0xffffffffu, v.y, 8);
    v.z += __shfl_xor_sync(0xffffffffu, v.z, 8);
    v.w += __shfl_xor_sync(0xffffffffu, v.w, 8);

    if (j < 4) {
        int c = j * 4;
        float4 b0 = *(const float4*)&bias[c];
        float4 b1 = *(const float4*)&bias[HID + c];
        float4 b2 = *(const float4*)&bias[2 * HID + c];
        float4 b3 = *(const float4*)&bias[3 * HID + c];
        float4 o;
        o.x = v.x + 0.25f * (b0.x + b1.x + b2.x + b3.x);
        o.y = v.y + 0.25f * (b0.y + b1.y + b2.y + b3.y);
        o.z = v.z + 0.25f * (b0.z + b1.z + b2.z + b3.z);
        o.w = v.w + 0.25f * (b0.w + b1.w + b2.w + b3.w);
        *(float4*)&out[n * HID + c] = o;
    }
}

// ---------------- launch ------------------------------------------------------
extern "C" void kernel_launch(void* const* d_in, const int* in_sizes, int n_in,
                              void* d_out, int out_size) {
    const float* features = (const float*)d_in[0];
    const float* W        = (const float*)d_in[1];
    const float* attn_l   = (const float*)d_in[2];
    const float* attn_r   = (const float*)d_in[3];
    const float* bias     = (const float*)d_in[4];
    const void*  src_raw  = d_in[5];
    const void*  dst_raw  = d_in[6];
    float* out = (float*)d_out;

    const int T = 256;

    k_convert<<<(N_EDGES + T - 1) / T, T>>>(src_raw, dst_raw);
    k_gemm<<<(N_NODES + BM - 1) / BM, T>>>(features, W, attn_l, attn_r);
    k_edge<<<((long long)N_EDGES * 16 + T - 1) / T, T>>>();
    k_final<<<(N_NODES * 16 + T - 1) / T, T>>>(bias, out);
}